// round 12
// baseline (speedup 1.0000x reference)
#include <cuda_runtime.h>
#include <cuda_fp16.h>
#include <cstdint>

// Problem constants
#define B_    8
#define C_IN  64
#define C_OUT 128
#define H_IN  256
#define W_IN  256
#define H_OUT 128
#define W_OUT 128
#define N_PTS 50000

#define WOB     64       // output-pixel tile per block (M=64)
#define CICHUNK 16       // ci per chunk (4 chunks); one k16 MMA per tap-chunk
#define XS_IW   130      // input cols: 2*64 + 2
#define ROWP    12       // words per row (8 fp16x2 + 4 pad): 12*lq+lr mod 32 injective
#define XS_WORDS (3 * XS_IW * ROWP)       // 4680 words = 18.7 KB
#define WS_WORDS (9 * C_OUT * ROWP)       // all 9 taps resident: 13824 words = 55.3 KB

// Scratch: conv output NHWC-flat [B*H_OUT*W_OUT, C_OUT] as fp16 (33.5 MB)
__device__ __align__(256) __half g_y[(size_t)B_ * H_OUT * W_OUT * C_OUT];
// Weights as fp16x2 words, [tap][co][ci/2] (ci pairs in natural order)
__device__ __align__(256) unsigned g_wH[9 * C_OUT * (C_IN / 2)];

// ---------------------------------------------------------------------------
// Kernel 0: weights (C_OUT,C_IN,3,3) -> fp16x2 [tap][co][ci/2]
// ---------------------------------------------------------------------------
__global__ void wt_kernel(const float* __restrict__ w) {
    int idx = blockIdx.x * blockDim.x + threadIdx.x;
    if (idx >= 9 * C_OUT * (C_IN / 2)) return;
    int pr  = idx % (C_IN / 2);
    int co  = (idx / (C_IN / 2)) % C_OUT;
    int tap = idx / ((C_IN / 2) * C_OUT);
    float w0 = w[(co * C_IN + 2 * pr) * 9 + tap];
    float w1 = w[(co * C_IN + 2 * pr + 1) * 9 + tap];
    __half2 h = __floats2half2_rn(w0, w1);
    g_wH[idx] = *(unsigned*)&h;
}

// ---------------------------------------------------------------------------
// Kernel 1: implicit-GEMM conv via mma.sync m16n8k16 fp16 (fp32 accum).
// Block: 256 thr (8 warps), tile M=64 pixels x N=128 co -> 3 blocks/SM.
// Warp (wm 0..1, wn 0..3): 32 rows x 32 cols = 2 m16 x 4 n8 frags (32 acc regs).
// Per ci-chunk: one cooperative fill of xs + ws (all 9 taps), then
// 9 taps x 8 MMAs from read-only smem. 2 syncs per chunk.
// ---------------------------------------------------------------------------
__global__ __launch_bounds__(256, 3) void conv_kernel(
    const float* __restrict__ x,
    const float* __restrict__ bias)
{
    extern __shared__ unsigned smem[];
    unsigned* xs = smem;                  // [3][XS_IW][ROWP] fp16x2 words
    unsigned* ws = smem + XS_WORDS;       // [9][C_OUT][ROWP] fp16x2 words

    const int wb = (blockIdx.x & 1) * WOB;       // wo tile base: 0 or 64
    const int ho = blockIdx.x >> 1;
    const int b  = blockIdx.y;
    const int t  = threadIdx.x;
    const int lane = t & 31, warp = t >> 5;
    const int wm = warp >> 2;        // 0..1  (32 m-rows each)
    const int wn = warp & 3;         // 0..3  (32 co each)
    const int lq = lane >> 2;        // 0..7
    const int lr = lane & 3;         // 0..3

    float acc[2][4][4] = {};

    for (int cc = 0; cc < C_IN; cc += CICHUNK) {
        __syncthreads();   // xs/ws free (prev chunk's MMAs done)
        // ---- fill xs: [3 kh][130 iw] x 16 ci as 8 fp16x2 words, pitch ROWP
        for (int i = t; i < 3 * XS_IW * 2; i += 256) {
            int half = i / (3 * XS_IW);             // ci half: 0 -> ci 0..7, 1 -> 8..15
            int rem  = i % (3 * XS_IW);
            int r    = rem / XS_IW;
            int iw   = rem % XS_IW;
            int ih   = 2 * ho - 1 + r;
            int iwg  = 2 * wb - 1 + iw;
            unsigned u[4] = {0, 0, 0, 0};
            if (ih >= 0 && ih < H_IN && iwg >= 0 && iwg < W_IN) {
                const float* p = &x[(((size_t)(b * C_IN + cc + half * 8)) * H_IN + ih) * W_IN + iwg];
                #pragma unroll
                for (int j = 0; j < 4; j++) {
                    float f0 = p[(size_t)(2 * j) * H_IN * W_IN];
                    float f1 = p[(size_t)(2 * j + 1) * H_IN * W_IN];
                    __half2 h = __floats2half2_rn(f0, f1);
                    u[j] = *(unsigned*)&h;
                }
            }
            *(uint4*)&xs[(r * XS_IW + iw) * ROWP + half * 4] = make_uint4(u[0], u[1], u[2], u[3]);
        }
        // ---- fill ws: all 9 taps x 128 co x 16 ci (2304 uint4, 9 per thread)
        #pragma unroll
        for (int j = 0; j < 9; j++) {
            int idx  = t + 256 * j;          // 0..2303
            int half = idx & 1;
            int tc   = idx >> 1;             // tap*128 + co
            uint4 v = *(const uint4*)&g_wH[tc * (C_IN / 2) + (cc / 2) + half * 4];
            *(uint4*)&ws[tc * ROWP + half * 4] = v;
        }
        __syncthreads();   // xs + ws ready

        #pragma unroll
        for (int tap = 0; tap < 9; tap++) {
            const int kh = tap / 3, kw = tap % 3;
            unsigned bf0[4], bf1[4];
            #pragma unroll
            for (int j8 = 0; j8 < 4; j8++) {
                const unsigned* br = &ws[(tap * C_OUT + wn * 32 + j8 * 8 + lq) * ROWP];
                bf0[j8] = br[lr];
                bf1[j8] = br[lr + 4];
            }
            #pragma unroll
            for (int i16 = 0; i16 < 2; i16++) {
                int m0 = wm * 32 + i16 * 16 + lq;
                const unsigned* xr0 = &xs[(kh * XS_IW + 2 * m0 + kw) * ROWP];
                const unsigned* xr1 = &xs[(kh * XS_IW + 2 * (m0 + 8) + kw) * ROWP];
                unsigned a0 = xr0[lr];
                unsigned a1 = xr1[lr];
                unsigned a2 = xr0[lr + 4];
                unsigned a3 = xr1[lr + 4];
                #pragma unroll
                for (int j8 = 0; j8 < 4; j8++) {
                    asm volatile(
                        "mma.sync.aligned.m16n8k16.row.col.f32.f16.f16.f32 "
                        "{%0,%1,%2,%3}, {%4,%5,%6,%7}, {%8,%9}, {%0,%1,%2,%3};"
                        : "+f"(acc[i16][j8][0]), "+f"(acc[i16][j8][1]),
                          "+f"(acc[i16][j8][2]), "+f"(acc[i16][j8][3])
                        : "r"(a0), "r"(a1), "r"(a2), "r"(a3),
                          "r"(bf0[j8]), "r"(bf1[j8]));
                }
            }
        }
    }

    // ---- epilogue: bias + ReLU -> g_y NHWC-flat fp16 (half2 per co-pair)
    size_t pixbase = ((size_t)(b * H_OUT + ho)) * W_OUT + wb;
    #pragma unroll
    for (int i16 = 0; i16 < 2; i16++) {
        int m0 = wm * 32 + i16 * 16 + lq;
        #pragma unroll
        for (int j8 = 0; j8 < 4; j8++) {
            int co = wn * 32 + j8 * 8 + 2 * lr;
            float b0 = bias[co], b1 = bias[co + 1];
            __half2 lo = __floats2half2_rn(fmaxf(acc[i16][j8][0] + b0, 0.f),
                                           fmaxf(acc[i16][j8][1] + b1, 0.f));
            __half2 hi = __floats2half2_rn(fmaxf(acc[i16][j8][2] + b0, 0.f),
                                           fmaxf(acc[i16][j8][3] + b1, 0.f));
            *(__half2*)&g_y[(pixbase + m0) * C_OUT + co]     = lo;
            *(__half2*)&g_y[(pixbase + m0 + 8) * C_OUT + co] = hi;
        }
    }
}

// ---------------------------------------------------------------------------
// Kernel 2: fused gather + flattened double segment-max + additive fusion.
// One warp per 3D point; range = [a_ptr[v_ptr[n]], a_ptr[v_ptr[n+1]]).
// Post-ReLU values >= 0 => 0-init max == reference empty-segment semantics.
// Lane handles 4 channels = 2 half2 (uint2 8B load); max in fp16 (exact),
// final add vs x3d in fp32.
// ---------------------------------------------------------------------------
__global__ __launch_bounds__(256) void pool_fuse_kernel(
    const float* __restrict__ x3d,
    const int*   __restrict__ fm_idx,
    const int*   __restrict__ a_ptr,
    const int*   __restrict__ v_ptr,
    float*       __restrict__ out)
{
    int warp = (blockIdx.x * blockDim.x + threadIdx.x) >> 5;
    int lane = threadIdx.x & 31;
    if (warp >= N_PTS) return;

    int lo = a_ptr[v_ptr[warp]];
    int hi = a_ptr[v_ptr[warp + 1]];

    __half2 acc0 = __float2half2_rn(0.f);
    __half2 acc1 = __float2half2_rn(0.f);
    int i = lo;
    for (; i + 4 <= hi; i += 4) {
        int r0 = fm_idx[i + 0];
        int r1 = fm_idx[i + 1];
        int r2 = fm_idx[i + 2];
        int r3 = fm_idx[i + 3];
        uint2 u0 = *(const uint2*)&g_y[(size_t)r0 * C_OUT + lane * 4];
        uint2 u1 = *(const uint2*)&g_y[(size_t)r1 * C_OUT + lane * 4];
        uint2 u2 = *(const uint2*)&g_y[(size_t)r2 * C_OUT + lane * 4];
        uint2 u3 = *(const uint2*)&g_y[(size_t)r3 * C_OUT + lane * 4];
        acc0 = __hmax2(__hmax2(acc0, *(__half2*)&u0.x),
                       __hmax2(*(__half2*)&u1.x,
                               __hmax2(*(__half2*)&u2.x, *(__half2*)&u3.x)));
        acc1 = __hmax2(__hmax2(acc1, *(__half2*)&u0.y),
                       __hmax2(*(__half2*)&u1.y,
                               __hmax2(*(__half2*)&u2.y, *(__half2*)&u3.y)));
    }
    for (; i < hi; i++) {
        int r = fm_idx[i];
        uint2 u = *(const uint2*)&g_y[(size_t)r * C_OUT + lane * 4];
        acc0 = __hmax2(acc0, *(__half2*)&u.x);
        acc1 = __hmax2(acc1, *(__half2*)&u.y);
    }

    float2 p0 = __half22float2(acc0);
    float2 p1 = __half22float2(acc1);
    float4 xv = *(const float4*)&x3d[(size_t)warp * C_OUT + lane * 4];
    *(float4*)&out[(size_t)warp * C_OUT + lane * 4] =
        make_float4(p0.x + xv.x, p0.y + xv.y, p1.x + xv.z, p1.y + xv.w);
}

// ---------------------------------------------------------------------------
// Launch: inputs x, w, b, x_3d, fm_idx, a_ptr, v_ptr
// ---------------------------------------------------------------------------
extern "C" void kernel_launch(void* const* d_in, const int* in_sizes, int n_in,
                              void* d_out, int out_size)
{
    const float* x      = (const float*)d_in[0];
    const float* w      = (const float*)d_in[1];
    const float* bias   = (const float*)d_in[2];
    const float* x3d    = (const float*)d_in[3];
    const int*   fm_idx = (const int*)d_in[4];
    const int*   a_ptr  = (const int*)d_in[5];
    const int*   v_ptr  = (const int*)d_in[6];
    float* out = (float*)d_out;

    wt_kernel<<<(9 * C_OUT * (C_IN / 2) + 255) / 256, 256>>>(w);

    const int smem_bytes = (XS_WORDS + WS_WORDS) * (int)sizeof(unsigned);   // 74 KB
    cudaFuncSetAttribute(conv_kernel, cudaFuncAttributeMaxDynamicSharedMemorySize, smem_bytes);
    dim3 cgrid(H_OUT * 2, B_);
    conv_kernel<<<cgrid, 256, smem_bytes>>>(x, bias);

    int nblocks = (N_PTS + 7) / 8;
    pool_fuse_kernel<<<nblocks, 256>>>(x3d, fm_idx, a_ptr, v_ptr, out);
}

// round 13
// speedup vs baseline: 1.1818x; 1.1818x over previous
#include <cuda_runtime.h>
#include <cuda_fp16.h>
#include <cstdint>

// Problem constants
#define B_    8
#define C_IN  64
#define C_OUT 128
#define H_IN  256
#define W_IN  256
#define H_OUT 128
#define W_OUT 128
#define N_PTS 50000

#define CICHUNK 16       // ci per chunk (4 chunks); one k16 MMA per tap-chunk
#define XS_IW   258      // input cols: 2*128 + 2
#define ROWP    12       // words per row (8 fp16x2 + 4 pad): 12*lq+lr mod 32 injective
#define XS_WORDS (3 * XS_IW * ROWP)       // 9288 words = 37.2 KB
#define WS_WORDS (9 * C_OUT * ROWP)       // all 9 taps resident: 13824 words = 55.3 KB

// Scratch: conv output NHWC-flat [B*H_OUT*W_OUT, C_OUT] as fp16 (33.5 MB)
__device__ __align__(256) __half g_y[(size_t)B_ * H_OUT * W_OUT * C_OUT];
// Weights as fp16x2 words, [tap][co][ci/2] (ci pairs in natural order)
__device__ __align__(256) unsigned g_wH[9 * C_OUT * (C_IN / 2)];

// ---------------------------------------------------------------------------
// Kernel 0: weights (C_OUT,C_IN,3,3) -> fp16x2 [tap][co][ci/2]
// ---------------------------------------------------------------------------
__global__ void wt_kernel(const float* __restrict__ w) {
    int idx = blockIdx.x * blockDim.x + threadIdx.x;
    if (idx >= 9 * C_OUT * (C_IN / 2)) return;
    int pr  = idx % (C_IN / 2);
    int co  = (idx / (C_IN / 2)) % C_OUT;
    int tap = idx / ((C_IN / 2) * C_OUT);
    float w0 = w[(co * C_IN + 2 * pr) * 9 + tap];
    float w1 = w[(co * C_IN + 2 * pr + 1) * 9 + tap];
    __half2 h = __floats2half2_rn(w0, w1);
    g_wH[idx] = *(unsigned*)&h;
}

// ---------------------------------------------------------------------------
// Kernel 1: implicit-GEMM conv via mma.sync m16n8k16 fp16 (fp32 accum).
// Block: 256 thr (8 warps), tile M=128 pixels (one ho row) x N=128 co.
// Warp (wm 0..3, wn 0..1): 32 rows x 64 cols = 2 m16 x 8 n8 frags.
// Per ci-chunk: one cooperative fill of xs + ws (all 9 taps), then
// 9 taps x 16 MMAs from read-only smem. (Proven R11 config — at the
// sm_103a mma.sync issue floor, ~32 cyc/SMSP per MMA.)
// ---------------------------------------------------------------------------
__global__ __launch_bounds__(256, 2) void conv_kernel(
    const float* __restrict__ x,
    const float* __restrict__ bias)
{
    extern __shared__ unsigned smem[];
    unsigned* xs = smem;                  // [3][XS_IW][ROWP] fp16x2 words
    unsigned* ws = smem + XS_WORDS;       // [9][C_OUT][ROWP] fp16x2 words

    const int ho = blockIdx.x;
    const int b  = blockIdx.y;
    const int t  = threadIdx.x;
    const int lane = t & 31, warp = t >> 5;
    const int wm = warp >> 1;        // 0..3  (32 m-rows each)
    const int wn = warp & 1;         // 0..1  (64 co each)
    const int lq = lane >> 2;        // 0..7
    const int lr = lane & 3;         // 0..3

    float acc[2][8][4] = {};

    for (int cc = 0; cc < C_IN; cc += CICHUNK) {
        __syncthreads();   // xs/ws free (prev chunk's MMAs done)
        // ---- fill xs: [3 kh][258 iw] x 16 ci as 8 fp16x2 words, pitch ROWP
        for (int i = t; i < 3 * XS_IW * 2; i += 256) {
            int half = i / (3 * XS_IW);             // ci half: 0 -> ci 0..7, 1 -> 8..15
            int rem  = i % (3 * XS_IW);
            int r    = rem / XS_IW;
            int iw   = rem % XS_IW;
            int ih   = 2 * ho - 1 + r;
            int iwg  = iw - 1;
            unsigned u[4] = {0, 0, 0, 0};
            if (ih >= 0 && ih < H_IN && iwg >= 0 && iwg < W_IN) {
                const float* p = &x[(((size_t)(b * C_IN + cc + half * 8)) * H_IN + ih) * W_IN + iwg];
                #pragma unroll
                for (int j = 0; j < 4; j++) {
                    float f0 = p[(size_t)(2 * j) * H_IN * W_IN];
                    float f1 = p[(size_t)(2 * j + 1) * H_IN * W_IN];
                    __half2 h = __floats2half2_rn(f0, f1);
                    u[j] = *(unsigned*)&h;
                }
            }
            *(uint4*)&xs[(r * XS_IW + iw) * ROWP + half * 4] = make_uint4(u[0], u[1], u[2], u[3]);
        }
        // ---- fill ws: all 9 taps x 128 co x 16 ci (2304 uint4, 9 per thread)
        #pragma unroll
        for (int j = 0; j < 9; j++) {
            int idx  = t + 256 * j;          // 0..2303
            int half = idx & 1;
            int tc   = idx >> 1;             // tap*128 + co
            uint4 v = *(const uint4*)&g_wH[tc * (C_IN / 2) + (cc / 2) + half * 4];
            *(uint4*)&ws[tc * ROWP + half * 4] = v;
        }
        __syncthreads();   // xs + ws ready

        #pragma unroll
        for (int tap = 0; tap < 9; tap++) {
            const int kh = tap / 3, kw = tap % 3;
            unsigned bf0[8], bf1[8];
            #pragma unroll
            for (int j8 = 0; j8 < 8; j8++) {
                const unsigned* br = &ws[(tap * C_OUT + wn * 64 + j8 * 8 + lq) * ROWP];
                bf0[j8] = br[lr];
                bf1[j8] = br[lr + 4];
            }
            #pragma unroll
            for (int i16 = 0; i16 < 2; i16++) {
                int m0 = wm * 32 + i16 * 16 + lq;
                const unsigned* xr0 = &xs[(kh * XS_IW + 2 * m0 + kw) * ROWP];
                const unsigned* xr1 = &xs[(kh * XS_IW + 2 * (m0 + 8) + kw) * ROWP];
                unsigned a0 = xr0[lr];
                unsigned a1 = xr1[lr];
                unsigned a2 = xr0[lr + 4];
                unsigned a3 = xr1[lr + 4];
                #pragma unroll
                for (int j8 = 0; j8 < 8; j8++) {
                    asm volatile(
                        "mma.sync.aligned.m16n8k16.row.col.f32.f16.f16.f32 "
                        "{%0,%1,%2,%3}, {%4,%5,%6,%7}, {%8,%9}, {%0,%1,%2,%3};"
                        : "+f"(acc[i16][j8][0]), "+f"(acc[i16][j8][1]),
                          "+f"(acc[i16][j8][2]), "+f"(acc[i16][j8][3])
                        : "r"(a0), "r"(a1), "r"(a2), "r"(a3),
                          "r"(bf0[j8]), "r"(bf1[j8]));
                }
            }
        }
    }

    // ---- epilogue: bias + ReLU -> g_y NHWC-flat fp16 (half2 per co-pair)
    size_t pixbase = ((size_t)(b * H_OUT + ho)) * W_OUT;
    #pragma unroll
    for (int i16 = 0; i16 < 2; i16++) {
        int m0 = wm * 32 + i16 * 16 + lq;
        #pragma unroll
        for (int j8 = 0; j8 < 8; j8++) {
            int co = wn * 64 + j8 * 8 + 2 * lr;
            float b0 = bias[co], b1 = bias[co + 1];
            __half2 lo = __floats2half2_rn(fmaxf(acc[i16][j8][0] + b0, 0.f),
                                           fmaxf(acc[i16][j8][1] + b1, 0.f));
            __half2 hi = __floats2half2_rn(fmaxf(acc[i16][j8][2] + b0, 0.f),
                                           fmaxf(acc[i16][j8][3] + b1, 0.f));
            *(__half2*)&g_y[(pixbase + m0) * C_OUT + co]     = lo;
            *(__half2*)&g_y[(pixbase + m0 + 8) * C_OUT + co] = hi;
        }
    }
}

// ---------------------------------------------------------------------------
// Kernel 2: fused gather + flattened double segment-max + additive fusion.
// One warp per 3D point; range = [a_ptr[v_ptr[n]], a_ptr[v_ptr[n+1]]).
// Post-ReLU values >= 0 => 0-init max == reference empty-segment semantics.
// 8-row software pipeline (16 outstanding 8B loads/warp) to cover L2 latency;
// max in fp16 (order-exact), final add vs x3d in fp32.
// ---------------------------------------------------------------------------
__global__ __launch_bounds__(256) void pool_fuse_kernel(
    const float* __restrict__ x3d,
    const int*   __restrict__ fm_idx,
    const int*   __restrict__ a_ptr,
    const int*   __restrict__ v_ptr,
    float*       __restrict__ out)
{
    int warp = (blockIdx.x * blockDim.x + threadIdx.x) >> 5;
    int lane = threadIdx.x & 31;
    if (warp >= N_PTS) return;

    int lo = a_ptr[v_ptr[warp]];
    int hi = a_ptr[v_ptr[warp + 1]];

    // pre-issue the x3d load (independent of the gather chain)
    float4 xv = *(const float4*)&x3d[(size_t)warp * C_OUT + lane * 4];

    __half2 acc0 = __float2half2_rn(0.f);
    __half2 acc1 = __float2half2_rn(0.f);
    int i = lo;
    for (; i + 8 <= hi; i += 8) {
        int r[8];
        #pragma unroll
        for (int j = 0; j < 8; j++) r[j] = fm_idx[i + j];
        uint2 u[8];
        #pragma unroll
        for (int j = 0; j < 8; j++)
            u[j] = *(const uint2*)&g_y[(size_t)r[j] * C_OUT + lane * 4];
        __half2 m0a = __hmax2(*(__half2*)&u[0].x, *(__half2*)&u[1].x);
        __half2 m0b = __hmax2(*(__half2*)&u[2].x, *(__half2*)&u[3].x);
        __half2 m0c = __hmax2(*(__half2*)&u[4].x, *(__half2*)&u[5].x);
        __half2 m0d = __hmax2(*(__half2*)&u[6].x, *(__half2*)&u[7].x);
        acc0 = __hmax2(acc0, __hmax2(__hmax2(m0a, m0b), __hmax2(m0c, m0d)));
        __half2 m1a = __hmax2(*(__half2*)&u[0].y, *(__half2*)&u[1].y);
        __half2 m1b = __hmax2(*(__half2*)&u[2].y, *(__half2*)&u[3].y);
        __half2 m1c = __hmax2(*(__half2*)&u[4].y, *(__half2*)&u[5].y);
        __half2 m1d = __hmax2(*(__half2*)&u[6].y, *(__half2*)&u[7].y);
        acc1 = __hmax2(acc1, __hmax2(__hmax2(m1a, m1b), __hmax2(m1c, m1d)));
    }
    for (; i < hi; i++) {
        int r = fm_idx[i];
        uint2 u = *(const uint2*)&g_y[(size_t)r * C_OUT + lane * 4];
        acc0 = __hmax2(acc0, *(__half2*)&u.x);
        acc1 = __hmax2(acc1, *(__half2*)&u.y);
    }

    float2 p0 = __half22float2(acc0);
    float2 p1 = __half22float2(acc1);
    *(float4*)&out[(size_t)warp * C_OUT + lane * 4] =
        make_float4(p0.x + xv.x, p0.y + xv.y, p1.x + xv.z, p1.y + xv.w);
}

// ---------------------------------------------------------------------------
// Launch: inputs x, w, b, x_3d, fm_idx, a_ptr, v_ptr
// ---------------------------------------------------------------------------
extern "C" void kernel_launch(void* const* d_in, const int* in_sizes, int n_in,
                              void* d_out, int out_size)
{
    const float* x      = (const float*)d_in[0];
    const float* w      = (const float*)d_in[1];
    const float* bias   = (const float*)d_in[2];
    const float* x3d    = (const float*)d_in[3];
    const int*   fm_idx = (const int*)d_in[4];
    const int*   a_ptr  = (const int*)d_in[5];
    const int*   v_ptr  = (const int*)d_in[6];
    float* out = (float*)d_out;

    wt_kernel<<<(9 * C_OUT * (C_IN / 2) + 255) / 256, 256>>>(w);

    const int smem_bytes = (XS_WORDS + WS_WORDS) * (int)sizeof(unsigned);   // 92.5 KB
    cudaFuncSetAttribute(conv_kernel, cudaFuncAttributeMaxDynamicSharedMemorySize, smem_bytes);
    dim3 cgrid(H_OUT, B_);
    conv_kernel<<<cgrid, 256, smem_bytes>>>(x, bias);

    int nblocks = (N_PTS + 7) / 8;
    pool_fuse_kernel<<<nblocks, 256>>>(x3d, fm_idx, a_ptr, v_ptr, out);
}

// round 14
// speedup vs baseline: 1.2886x; 1.0904x over previous
#include <cuda_runtime.h>
#include <cuda_fp16.h>
#include <cstdint>

// Problem constants
#define B_    8
#define C_IN  64
#define C_OUT 128
#define H_IN  256
#define W_IN  256
#define H_OUT 128
#define W_OUT 128
#define N_PTS 50000

#define CICHUNK 16       // ci per chunk (4 chunks); one k16 MMA per tap-chunk
#define XS_IW   258      // input cols: 2*128 + 2
#define ROWP    12       // words per row (8 fp16x2 + 4 pad): 12*lq+lr mod 32 injective
#define XS_WORDS (3 * XS_IW * ROWP)       // 9288 words = 37.2 KB
#define WS_WORDS (9 * C_OUT * ROWP)       // all 9 taps resident: 13824 words = 55.3 KB

// Scratch: conv output NHWC-flat [B*H_OUT*W_OUT, C_OUT] as fp16 (33.5 MB)
__device__ __align__(256) __half g_y[(size_t)B_ * H_OUT * W_OUT * C_OUT];
// Weights as fp16x2 words, [tap][co][ci/2] (ci pairs in natural order)
__device__ __align__(256) unsigned g_wH[9 * C_OUT * (C_IN / 2)];

// ---------------------------------------------------------------------------
// Kernel 0: weights (C_OUT,C_IN,3,3) -> fp16x2 [tap][co][ci/2]
// ---------------------------------------------------------------------------
__global__ void wt_kernel(const float* __restrict__ w) {
    int idx = blockIdx.x * blockDim.x + threadIdx.x;
    if (idx >= 9 * C_OUT * (C_IN / 2)) return;
    int pr  = idx % (C_IN / 2);
    int co  = (idx / (C_IN / 2)) % C_OUT;
    int tap = idx / ((C_IN / 2) * C_OUT);
    float w0 = w[(co * C_IN + 2 * pr) * 9 + tap];
    float w1 = w[(co * C_IN + 2 * pr + 1) * 9 + tap];
    __half2 h = __floats2half2_rn(w0, w1);
    g_wH[idx] = *(unsigned*)&h;
}

// ---------------------------------------------------------------------------
// Kernel 1: implicit-GEMM conv via mma.sync m16n8k16 fp16 (fp32 accum).
// Block: 512 thr (16 warps), tile M=128 pixels (one ho row) x N=128 co.
// Warp (wm 0..3, wn 0..3): 32 rows x 32 cols = 2 m16 x 4 n8 frags.
// Same tile/traffic as the R11 config but 32 warps/SM (2 blocks x 16) to
// absorb the chunk-boundary fill latency. Per ci-chunk: one cooperative
// fill of xs + ws (all 9 taps), then 9 taps x 8 MMAs from read-only smem.
// ---------------------------------------------------------------------------
__global__ __launch_bounds__(512, 2) void conv_kernel(
    const float* __restrict__ x,
    const float* __restrict__ bias)
{
    extern __shared__ unsigned smem[];
    unsigned* xs = smem;                  // [3][XS_IW][ROWP] fp16x2 words
    unsigned* ws = smem + XS_WORDS;       // [9][C_OUT][ROWP] fp16x2 words

    const int ho = blockIdx.x;
    const int b  = blockIdx.y;
    const int t  = threadIdx.x;
    const int lane = t & 31, warp = t >> 5;
    const int wm = warp >> 2;        // 0..3  (32 m-rows each)
    const int wn = warp & 3;         // 0..3  (32 co each)
    const int lq = lane >> 2;        // 0..7
    const int lr = lane & 3;         // 0..3

    float acc[2][4][4] = {};

    for (int cc = 0; cc < C_IN; cc += CICHUNK) {
        __syncthreads();   // xs/ws free (prev chunk's MMAs done)
        // ---- fill xs: [3 kh][258 iw] x 16 ci as 8 fp16x2 words, pitch ROWP
        for (int i = t; i < 3 * XS_IW * 2; i += 512) {
            int half = i / (3 * XS_IW);             // ci half: 0 -> ci 0..7, 1 -> 8..15
            int rem  = i % (3 * XS_IW);
            int r    = rem / XS_IW;
            int iw   = rem % XS_IW;
            int ih   = 2 * ho - 1 + r;
            int iwg  = iw - 1;
            unsigned u[4] = {0, 0, 0, 0};
            if (ih >= 0 && ih < H_IN && iwg >= 0 && iwg < W_IN) {
                const float* p = &x[(((size_t)(b * C_IN + cc + half * 8)) * H_IN + ih) * W_IN + iwg];
                #pragma unroll
                for (int j = 0; j < 4; j++) {
                    float f0 = p[(size_t)(2 * j) * H_IN * W_IN];
                    float f1 = p[(size_t)(2 * j + 1) * H_IN * W_IN];
                    __half2 h = __floats2half2_rn(f0, f1);
                    u[j] = *(unsigned*)&h;
                }
            }
            *(uint4*)&xs[(r * XS_IW + iw) * ROWP + half * 4] = make_uint4(u[0], u[1], u[2], u[3]);
        }
        // ---- fill ws: all 9 taps x 128 co x 16 ci (2304 uint4 over 512 thr)
        #pragma unroll
        for (int j = 0; j < 5; j++) {
            int idx = t + 512 * j;           // 0..2559, valid < 2304
            if (idx < 2304) {
                int half = idx & 1;
                int tc   = idx >> 1;         // tap*128 + co
                uint4 v = *(const uint4*)&g_wH[tc * (C_IN / 2) + (cc / 2) + half * 4];
                *(uint4*)&ws[tc * ROWP + half * 4] = v;
            }
        }
        __syncthreads();   // xs + ws ready

        #pragma unroll
        for (int tap = 0; tap < 9; tap++) {
            const int kh = tap / 3, kw = tap % 3;
            unsigned bf0[4], bf1[4];
            #pragma unroll
            for (int j8 = 0; j8 < 4; j8++) {
                const unsigned* br = &ws[(tap * C_OUT + wn * 32 + j8 * 8 + lq) * ROWP];
                bf0[j8] = br[lr];
                bf1[j8] = br[lr + 4];
            }
            #pragma unroll
            for (int i16 = 0; i16 < 2; i16++) {
                int m0 = wm * 32 + i16 * 16 + lq;
                const unsigned* xr0 = &xs[(kh * XS_IW + 2 * m0 + kw) * ROWP];
                const unsigned* xr1 = &xs[(kh * XS_IW + 2 * (m0 + 8) + kw) * ROWP];
                unsigned a0 = xr0[lr];
                unsigned a1 = xr1[lr];
                unsigned a2 = xr0[lr + 4];
                unsigned a3 = xr1[lr + 4];
                #pragma unroll
                for (int j8 = 0; j8 < 4; j8++) {
                    asm volatile(
                        "mma.sync.aligned.m16n8k16.row.col.f32.f16.f16.f32 "
                        "{%0,%1,%2,%3}, {%4,%5,%6,%7}, {%8,%9}, {%0,%1,%2,%3};"
                        : "+f"(acc[i16][j8][0]), "+f"(acc[i16][j8][1]),
                          "+f"(acc[i16][j8][2]), "+f"(acc[i16][j8][3])
                        : "r"(a0), "r"(a1), "r"(a2), "r"(a3),
                          "r"(bf0[j8]), "r"(bf1[j8]));
                }
            }
        }
    }

    // ---- epilogue: bias + ReLU -> g_y NHWC-flat fp16 (half2 per co-pair)
    size_t pixbase = ((size_t)(b * H_OUT + ho)) * W_OUT;
    #pragma unroll
    for (int i16 = 0; i16 < 2; i16++) {
        int m0 = wm * 32 + i16 * 16 + lq;
        #pragma unroll
        for (int j8 = 0; j8 < 4; j8++) {
            int co = wn * 32 + j8 * 8 + 2 * lr;
            float b0 = bias[co], b1 = bias[co + 1];
            __half2 lo = __floats2half2_rn(fmaxf(acc[i16][j8][0] + b0, 0.f),
                                           fmaxf(acc[i16][j8][1] + b1, 0.f));
            __half2 hi = __floats2half2_rn(fmaxf(acc[i16][j8][2] + b0, 0.f),
                                           fmaxf(acc[i16][j8][3] + b1, 0.f));
            *(__half2*)&g_y[(pixbase + m0) * C_OUT + co]     = lo;
            *(__half2*)&g_y[(pixbase + m0 + 8) * C_OUT + co] = hi;
        }
    }
}

// ---------------------------------------------------------------------------
// Kernel 2: fused gather + flattened double segment-max + additive fusion.
// One warp per 3D point; range = [a_ptr[v_ptr[n]], a_ptr[v_ptr[n+1]]).
// Post-ReLU values >= 0 => 0-init max == reference empty-segment semantics.
// 8-row software pipeline (16 outstanding 8B loads/warp) to cover L2 latency;
// max in fp16 (order-exact), final add vs x3d in fp32.
// ---------------------------------------------------------------------------
__global__ __launch_bounds__(256) void pool_fuse_kernel(
    const float* __restrict__ x3d,
    const int*   __restrict__ fm_idx,
    const int*   __restrict__ a_ptr,
    const int*   __restrict__ v_ptr,
    float*       __restrict__ out)
{
    int warp = (blockIdx.x * blockDim.x + threadIdx.x) >> 5;
    int lane = threadIdx.x & 31;
    if (warp >= N_PTS) return;

    int lo = a_ptr[v_ptr[warp]];
    int hi = a_ptr[v_ptr[warp + 1]];

    // pre-issue the x3d load (independent of the gather chain)
    float4 xv = *(const float4*)&x3d[(size_t)warp * C_OUT + lane * 4];

    __half2 acc0 = __float2half2_rn(0.f);
    __half2 acc1 = __float2half2_rn(0.f);
    int i = lo;
    for (; i + 8 <= hi; i += 8) {
        int r[8];
        #pragma unroll
        for (int j = 0; j < 8; j++) r[j] = fm_idx[i + j];
        uint2 u[8];
        #pragma unroll
        for (int j = 0; j < 8; j++)
            u[j] = *(const uint2*)&g_y[(size_t)r[j] * C_OUT + lane * 4];
        __half2 m0a = __hmax2(*(__half2*)&u[0].x, *(__half2*)&u[1].x);
        __half2 m0b = __hmax2(*(__half2*)&u[2].x, *(__half2*)&u[3].x);
        __half2 m0c = __hmax2(*(__half2*)&u[4].x, *(__half2*)&u[5].x);
        __half2 m0d = __hmax2(*(__half2*)&u[6].x, *(__half2*)&u[7].x);
        acc0 = __hmax2(acc0, __hmax2(__hmax2(m0a, m0b), __hmax2(m0c, m0d)));
        __half2 m1a = __hmax2(*(__half2*)&u[0].y, *(__half2*)&u[1].y);
        __half2 m1b = __hmax2(*(__half2*)&u[2].y, *(__half2*)&u[3].y);
        __half2 m1c = __hmax2(*(__half2*)&u[4].y, *(__half2*)&u[5].y);
        __half2 m1d = __hmax2(*(__half2*)&u[6].y, *(__half2*)&u[7].y);
        acc1 = __hmax2(acc1, __hmax2(__hmax2(m1a, m1b), __hmax2(m1c, m1d)));
    }
    for (; i < hi; i++) {
        int r = fm_idx[i];
        uint2 u = *(const uint2*)&g_y[(size_t)r * C_OUT + lane * 4];
        acc0 = __hmax2(acc0, *(__half2*)&u.x);
        acc1 = __hmax2(acc1, *(__half2*)&u.y);
    }

    float2 p0 = __half22float2(acc0);
    float2 p1 = __half22float2(acc1);
    *(float4*)&out[(size_t)warp * C_OUT + lane * 4] =
        make_float4(p0.x + xv.x, p0.y + xv.y, p1.x + xv.z, p1.y + xv.w);
}

// ---------------------------------------------------------------------------
// Launch: inputs x, w, b, x_3d, fm_idx, a_ptr, v_ptr
// ---------------------------------------------------------------------------
extern "C" void kernel_launch(void* const* d_in, const int* in_sizes, int n_in,
                              void* d_out, int out_size)
{
    const float* x      = (const float*)d_in[0];
    const float* w      = (const float*)d_in[1];
    const float* bias   = (const float*)d_in[2];
    const float* x3d    = (const float*)d_in[3];
    const int*   fm_idx = (const int*)d_in[4];
    const int*   a_ptr  = (const int*)d_in[5];
    const int*   v_ptr  = (const int*)d_in[6];
    float* out = (float*)d_out;

    wt_kernel<<<(9 * C_OUT * (C_IN / 2) + 255) / 256, 256>>>(w);

    const int smem_bytes = (XS_WORDS + WS_WORDS) * (int)sizeof(unsigned);   // 92.5 KB
    cudaFuncSetAttribute(conv_kernel, cudaFuncAttributeMaxDynamicSharedMemorySize, smem_bytes);
    dim3 cgrid(H_OUT, B_);
    conv_kernel<<<cgrid, 512, smem_bytes>>>(x, bias);

    int nblocks = (N_PTS + 7) / 8;
    pool_fuse_kernel<<<nblocks, 256>>>(x3d, fm_idx, a_ptr, v_ptr, out);
}